// round 13
// baseline (speedup 1.0000x reference)
#include <cuda_runtime.h>
#include <cuda_bf16.h>
#include <stdint.h>
#include <math.h>

// ---------------- problem dims ----------------
#define BB    512
#define TT    64
#define EE    512
#define HH    1024
#define G4    4096
#define NIMG  2048
#define VOCAB 10000

// ---------------- device scratch (no allocation allowed) ----------------
__device__ float          d_Xg[(size_t)TT * BB * G4];   // [T*B,4H] fp32, permuted gate order
__device__ float          d_c[BB * HH];
__device__ __nv_bfloat16  d_hhi[2][BB * HH];
__device__ __nv_bfloat16  d_hlo[2][BB * HH];
__device__ int            d_tok[TT * BB];
__device__ float          d_bsum[G4];
__device__ __nv_bfloat16  d_wih_hi[G4 * EE],    d_wih_lo[G4 * EE];
__device__ __nv_bfloat16  d_whh_hi[G4 * HH],    d_whh_lo[G4 * HH];
__device__ __nv_bfloat16  d_wout_hi[NIMG * HH], d_wout_lo[NIMG * HH];
__device__ __nv_bfloat16  d_emb_hi[VOCAB * EE], d_emb_lo[VOCAB * EE];

// ---------------- PTX helpers (all valid in compute_103 baseline PTX) ------
__device__ __forceinline__ uint32_t smem_u32(const void* p) {
    uint32_t a;
    asm("{ .reg .u64 t; cvta.to.shared.u64 t, %1; cvt.u32.u64 %0, t; }" : "=r"(a) : "l"(p));
    return a;
}
#define CP_ASYNC16(dst, src) \
    asm volatile("cp.async.cg.shared.global.L2::128B [%0], [%1], 16;" :: "r"(dst), "l"(src))
#define CP_COMMIT() asm volatile("cp.async.commit_group;" ::: "memory")
template<int n> __device__ __forceinline__ void cp_wait() {
    asm volatile("cp.async.wait_group %0;" :: "n"(n) : "memory");
}
#define LDMATRIX_X4(r0, r1, r2, r3, addr) \
    asm volatile("ldmatrix.sync.aligned.m8n8.x4.shared.b16 {%0,%1,%2,%3}, [%4];" \
        : "=r"(r0), "=r"(r1), "=r"(r2), "=r"(r3) : "r"(addr))
#define MMA_BF16(c, a, b) \
    asm volatile("mma.sync.aligned.m16n8k16.row.col.f32.bf16.bf16.f32 " \
        "{%0,%1,%2,%3}, {%4,%5,%6,%7}, {%8,%9}, {%0,%1,%2,%3};" \
        : "+f"((c)[0]), "+f"((c)[1]), "+f"((c)[2]), "+f"((c)[3]) \
        : "r"((a)[0]), "r"((a)[1]), "r"((a)[2]), "r"((a)[3]), "r"((b)[0]), "r"((b)[1]))

__device__ __forceinline__ float sigf(float x) { return 1.0f / (1.0f + __expf(-x)); }

// ---------------- bf16-split HMMA GEMM ----------------
// C[M,N] = (Ahi+Alo)[M,K] * (Bhi+Blo)[N,K]^T  via hi*hi + hi*lo + lo*hi, fp32 accum.
// CTA tile 128x128, BK=64, 8 warps (2 M x 4 N), warp tile 64x32.
// MODE 0: outp = C + bias (fp32). MODE 1: fused LSTM cell (gates interleaved per unit).
// GATHER: A rows are emb[tok[bm+row]].
#define SMEM_BYTES (2 * 4 * 16384)   // 131072: 2 bufs x {Ahi,Alo,Bhi,Blo} x 16KB

template<int KDIM, int MODE, bool GATHER>
__global__ __launch_bounds__(256, 1)
void hgemm(const __nv_bfloat16* __restrict__ Ahi, const __nv_bfloat16* __restrict__ Alo,
           const __nv_bfloat16* __restrict__ Bhi, const __nv_bfloat16* __restrict__ Blo,
           const float* __restrict__ bias, const float* __restrict__ xg,
           float* __restrict__ outp,
           float* __restrict__ cst, __nv_bfloat16* __restrict__ hhi, __nv_bfloat16* __restrict__ hlo,
           int N, const int* __restrict__ tok)
{
    extern __shared__ __align__(1024) char smem[];
    const uint32_t sb = smem_u32(smem);
    const int tid  = threadIdx.x;
    const int wid  = tid >> 5, lane = tid & 31;
    const int wm   = wid & 1,  wn   = wid >> 1;
    const int bm   = blockIdx.y * 128, bn = blockIdx.x * 128;
    constexpr int NC = KDIM / 64;

    // ---- loader setup: 16 cp.async of 16B per thread per chunk ----
    const int lrow = tid >> 3;   // 0..31
    const int lj   = tid & 7;    // 16B chunk within 128B row
    size_t arow[4];
#pragma unroll
    for (int q = 0; q < 4; ++q)
        arow[q] = GATHER ? (size_t)tok[bm + q * 32 + lrow] : (size_t)(bm + q * 32 + lrow);

    auto load_chunk = [&](int ch, int buf) {
        const int k0 = ch << 6;
#pragma unroll
        for (int i = 0; i < 16; ++i) {
            const int t = i >> 2, q = i & 3;
            const int row = q * 32 + lrow;
            const __nv_bfloat16* base;
            size_t grow;
            if      (t == 0) { base = Ahi; grow = arow[q]; }
            else if (t == 1) { base = Alo; grow = arow[q]; }
            else if (t == 2) { base = Bhi; grow = (size_t)(bn + row); }
            else             { base = Blo; grow = (size_t)(bn + row); }
            const char* src = (const char*)base + (grow * KDIM + k0) * 2 + lj * 16;
            uint32_t off = (uint32_t)(row * 128 + lj * 16);
            off ^= ((off >> 3) & 0x70);
            CP_ASYNC16(sb + (uint32_t)(buf * 65536 + t * 16384) + off, src);
        }
        CP_COMMIT();
    };

    float acc[4][4][4];
#pragma unroll
    for (int im = 0; im < 4; ++im)
#pragma unroll
        for (int in_ = 0; in_ < 4; ++in_)
#pragma unroll
            for (int r = 0; r < 4; ++r) acc[im][in_][r] = 0.0f;

    // ---- pipelined main loop ----
    load_chunk(0, 0);
    for (int ch = 0; ch < NC; ++ch) {
        if (ch + 1 < NC) { load_chunk(ch + 1, (ch + 1) & 1); cp_wait<1>(); }
        else             { cp_wait<0>(); }
        __syncthreads();

        const uint32_t base_buf = sb + (uint32_t)((ch & 1) * 65536);
#pragma unroll
        for (int p = 0; p < 3; ++p) {
            const uint32_t Ab = base_buf + ((p == 2) ? 16384u : 0u);          // Alo : Ahi
            const uint32_t Bb = base_buf + ((p == 1) ? 49152u : 32768u);      // Blo : Bhi
#pragma unroll
            for (int ks = 0; ks < 4; ++ks) {
                uint32_t a[4][4];
#pragma unroll
                for (int im = 0; im < 4; ++im) {
                    const int r  = wm * 64 + im * 16 + ((lane >> 3) & 1) * 8 + (lane & 7);
                    const int cb = ks * 32 + ((lane >> 4) & 1) * 16;
                    uint32_t off = (uint32_t)(r * 128 + cb);
                    off ^= ((off >> 3) & 0x70);
                    LDMATRIX_X4(a[im][0], a[im][1], a[im][2], a[im][3], Ab + off);
                }
                uint32_t b[4][2];
#pragma unroll
                for (int ib = 0; ib < 2; ++ib) {
                    const int r  = wn * 32 + ib * 16 + ((lane >> 4) & 1) * 8 + (lane & 7);
                    const int cb = ks * 32 + ((lane >> 3) & 1) * 16;
                    uint32_t off = (uint32_t)(r * 128 + cb);
                    off ^= ((off >> 3) & 0x70);
                    uint32_t t0, t1, t2, t3;
                    LDMATRIX_X4(t0, t1, t2, t3, Bb + off);
                    b[2 * ib][0] = t0; b[2 * ib][1] = t1;
                    b[2 * ib + 1][0] = t2; b[2 * ib + 1][1] = t3;
                }
#pragma unroll
                for (int im = 0; im < 4; ++im)
#pragma unroll
                    for (int in_ = 0; in_ < 4; ++in_)
                        MMA_BF16(acc[im][in_], a[im], b[in_]);
            }
        }
        __syncthreads();
    }

    // ---- epilogue ----
    if (MODE == 0) {
#pragma unroll
        for (int im = 0; im < 4; ++im) {
#pragma unroll
            for (int in_ = 0; in_ < 4; ++in_) {
                const int row = bm + wm * 64 + im * 16 + (lane >> 2);
                const int col = bn + wn * 32 + in_ * 8 + 2 * (lane & 3);
                const float b0 = bias ? bias[col] : 0.0f;
                const float b1 = bias ? bias[col + 1] : 0.0f;
                float* p0 = outp + (size_t)row * N + col;
                float* p1 = outp + (size_t)(row + 8) * N + col;
                *(float2*)p0 = make_float2(acc[im][in_][0] + b0, acc[im][in_][1] + b1);
                *(float2*)p1 = make_float2(acc[im][in_][2] + b0, acc[im][in_][3] + b1);
            }
        }
    } else {
        // stage gates tile [128][128] fp32 in smem (row stride 132 to dodge conflicts)
        float* gs = (float*)smem;
#pragma unroll
        for (int im = 0; im < 4; ++im) {
#pragma unroll
            for (int in_ = 0; in_ < 4; ++in_) {
                const int row = wm * 64 + im * 16 + (lane >> 2);
                const int col = wn * 32 + in_ * 8 + 2 * (lane & 3);
                gs[row * 132 + col]       = acc[im][in_][0];
                gs[row * 132 + col + 1]   = acc[im][in_][1];
                gs[(row + 8) * 132 + col]     = acc[im][in_][2];
                gs[(row + 8) * 132 + col + 1] = acc[im][in_][3];
            }
        }
        __syncthreads();
        // pointwise LSTM: 128 rows x 32 units per CTA
#pragma unroll
        for (int it = 0; it < 16; ++it) {
            const int idx = tid + it * 256;
            const int row = idx >> 5;
            const int u   = idx & 31;
            const float g0 = gs[row * 132 + 4 * u];
            const float g1 = gs[row * 132 + 4 * u + 1];
            const float g2 = gs[row * 132 + 4 * u + 2];
            const float g3 = gs[row * 132 + 4 * u + 3];
            const float4 x = *(const float4*)(xg + (size_t)(bm + row) * G4 + bn + 4 * u);
            const float ig = sigf(g0 + x.x);
            const float fg = sigf(g1 + x.y);
            const float gg = tanhf(g2 + x.z);
            const float og = sigf(g3 + x.w);
            const size_t cidx = (size_t)(bm + row) * HH + (bn >> 2) + u;
            const float cn = fg * cst[cidx] + ig * gg;
            cst[cidx] = cn;
            const float h = og * tanhf(cn);
            const __nv_bfloat16 hi = __float2bfloat16_rn(h);
            hhi[cidx] = hi;
            hlo[cidx] = __float2bfloat16_rn(h - __bfloat162float(hi));
        }
    }
}

// ---------------- packing kernels ----------------
__device__ __forceinline__ void split_store(float x, __nv_bfloat16* hi, __nv_bfloat16* lo, size_t i) {
    const __nv_bfloat16 h = __float2bfloat16_rn(x);
    hi[i] = h;
    lo[i] = __float2bfloat16_rn(x - __bfloat162float(h));
}

__global__ void pack_weights(const float* __restrict__ W_ih, const float* __restrict__ W_hh,
                             const float* __restrict__ W_out,
                             const float* __restrict__ b_ih, const float* __restrict__ b_hh)
{
    const size_t idx = (size_t)blockIdx.x * blockDim.x + threadIdx.x;
    if (idx < (size_t)G4 * HH) {   // W_hh permuted rows: row n <- src (n&3)*HH + (n>>2)
        const int n = (int)(idx >> 10), k = (int)(idx & 1023);
        const int gt = n & 3, u = n >> 2;
        split_store(W_hh[(size_t)(gt * HH + u) * HH + k], d_whh_hi, d_whh_lo, idx);
    }
    if (idx < (size_t)G4 * EE) {   // W_ih permuted rows
        const int n = (int)(idx >> 9), k = (int)(idx & 511);
        const int gt = n & 3, u = n >> 2;
        split_store(W_ih[(size_t)(gt * HH + u) * EE + k], d_wih_hi, d_wih_lo, idx);
    }
    if (idx < (size_t)NIMG * HH) {
        split_store(W_out[idx], d_wout_hi, d_wout_lo, idx);
    }
    if (idx < G4) {
        const int gt = (int)idx & 3, u = (int)idx >> 2;
        d_bsum[idx] = b_ih[gt * HH + u] + b_hh[gt * HH + u];
    }
}

__global__ void pack_emb(const float* __restrict__ emb)
{
    const size_t idx = (size_t)blockIdx.x * blockDim.x + threadIdx.x;
    if (idx < (size_t)VOCAB * EE) split_store(emb[idx], d_emb_hi, d_emb_lo, idx);
}

__global__ void prep_kernel(const int* __restrict__ m)
{
    const int idx = blockIdx.x * blockDim.x + threadIdx.x;
    if (idx < BB * HH) {
        d_hhi[0][idx] = __float2bfloat16_rn(0.0f);
        d_hlo[0][idx] = __float2bfloat16_rn(0.0f);
        d_c[idx] = 0.0f;
    }
    if (idx < TT * BB) {
        const int t = idx / BB, b = idx % BB;
        d_tok[idx] = m[b * TT + t];   // m is [B, T]
    }
}

// ---------------- launch ----------------
extern "C" void kernel_launch(void* const* d_in, const int* in_sizes, int n_in,
                              void* d_out, int out_size)
{
    const int*   m     = (const int*)  d_in[0];
    const float* emb   = (const float*)d_in[1];
    const float* W_ih  = (const float*)d_in[2];
    const float* W_hh  = (const float*)d_in[3];
    const float* b_ih  = (const float*)d_in[4];
    const float* b_hh  = (const float*)d_in[5];
    const float* W_out = (const float*)d_in[6];
    const float* b_out = (const float*)d_in[7];
    float* out = (float*)d_out;

    float *Xg, *cst, *bsum; int* tok;
    __nv_bfloat16 *hhi0, *hlo0, *hhi1, *hlo1;
    __nv_bfloat16 *wih_hi, *wih_lo, *whh_hi, *whh_lo, *wout_hi, *wout_lo, *emb_hi, *emb_lo;
    cudaGetSymbolAddress((void**)&Xg,   d_Xg);
    cudaGetSymbolAddress((void**)&cst,  d_c);
    cudaGetSymbolAddress((void**)&bsum, d_bsum);
    cudaGetSymbolAddress((void**)&tok,  d_tok);
    {
        __nv_bfloat16* p;
        cudaGetSymbolAddress((void**)&p, d_hhi); hhi0 = p; hhi1 = p + BB * HH;
        cudaGetSymbolAddress((void**)&p, d_hlo); hlo0 = p; hlo1 = p + BB * HH;
        cudaGetSymbolAddress((void**)&p, d_wih_hi);  wih_hi = p;
        cudaGetSymbolAddress((void**)&p, d_wih_lo);  wih_lo = p;
        cudaGetSymbolAddress((void**)&p, d_whh_hi);  whh_hi = p;
        cudaGetSymbolAddress((void**)&p, d_whh_lo);  whh_lo = p;
        cudaGetSymbolAddress((void**)&p, d_wout_hi); wout_hi = p;
        cudaGetSymbolAddress((void**)&p, d_wout_lo); wout_lo = p;
        cudaGetSymbolAddress((void**)&p, d_emb_hi);  emb_hi = p;
        cudaGetSymbolAddress((void**)&p, d_emb_lo);  emb_lo = p;
    }

    cudaFuncSetAttribute(hgemm<EE, 0, true>,   cudaFuncAttributeMaxDynamicSharedMemorySize, SMEM_BYTES);
    cudaFuncSetAttribute(hgemm<HH, 1, false>,  cudaFuncAttributeMaxDynamicSharedMemorySize, SMEM_BYTES);
    cudaFuncSetAttribute(hgemm<HH, 0, false>,  cudaFuncAttributeMaxDynamicSharedMemorySize, SMEM_BYTES);

    // 1) prep + packing
    prep_kernel<<<(BB * HH + 255) / 256, 256>>>(m);
    pack_weights<<<(G4 * HH + 255) / 256, 256>>>(W_ih, W_hh, W_out, b_ih, b_hh);
    pack_emb<<<(VOCAB * EE + 255) / 256, 256>>>(emb);

    // 2) Xg = gather(emb)[T*B, E] @ W_ih^T + bsum   (permuted gate order)
    {
        dim3 grid(G4 / 128, (TT * BB) / 128);   // 32 x 256
        hgemm<EE, 0, true><<<grid, 256, SMEM_BYTES>>>(
            emb_hi, emb_lo, wih_hi, wih_lo, bsum, nullptr, Xg,
            nullptr, nullptr, nullptr, G4, tok);
    }

    // 3) recurrent loop: fused GEMM+LSTM per step, h double-buffered
    {
        dim3 grid(G4 / 128, BB / 128);          // 32 x 4
        for (int t = 0; t < TT; ++t) {
            const int in  = t & 1;
            __nv_bfloat16* ahi = in ? hhi1 : hhi0;
            __nv_bfloat16* alo = in ? hlo1 : hlo0;
            __nv_bfloat16* ohi = in ? hhi0 : hhi1;
            __nv_bfloat16* olo = in ? hlo0 : hlo1;
            hgemm<HH, 1, false><<<grid, 256, SMEM_BYTES>>>(
                ahi, alo, whh_hi, whh_lo, nullptr, Xg + (size_t)t * BB * G4, nullptr,
                cst, ohi, olo, G4, nullptr);
        }
    }

    // 4) out = h @ W_out^T + b_out   (after 64 steps final h is in buffer 0)
    {
        dim3 grid(NIMG / 128, BB / 128);        // 16 x 4
        hgemm<HH, 0, false><<<grid, 256, SMEM_BYTES>>>(
            hhi0, hlo0, wout_hi, wout_lo, b_out, nullptr, out,
            nullptr, nullptr, nullptr, NIMG, nullptr);
    }
}

// round 16
// speedup vs baseline: 1.3857x; 1.3857x over previous
#include <cuda_runtime.h>
#include <cuda_bf16.h>
#include <stdint.h>
#include <string.h>
#include <math.h>

// ---------------- problem dims ----------------
#define BB    512
#define TT    64
#define EE    512
#define HH    1024
#define G4    4096
#define NIMG  2048
#define VOCAB 10000
#define MVPAD 10112          // 79 * 128

// ---------------- device scratch (no allocation allowed) ----------------
__device__ __align__(256) float          d_Xg[(size_t)MVPAD * G4];   // per-VOCAB gate table (+bias), permuted
__device__ __align__(256) float          d_c[BB * HH];
__device__ __align__(256) __nv_bfloat16  d_hhi[2][BB * HH];
__device__ __align__(256) __nv_bfloat16  d_hlo[2][BB * HH];
__device__ __align__(256) int            d_tok[TT * BB];
__device__ __align__(256) float          d_bsum[G4];
__device__ __align__(256) __nv_bfloat16  d_wih_hi[G4 * EE],    d_wih_lo[G4 * EE];
__device__ __align__(256) __nv_bfloat16  d_whh_hi[G4 * HH],    d_whh_lo[G4 * HH];
__device__ __align__(256) __nv_bfloat16  d_wout_hi[NIMG * HH], d_wout_lo[NIMG * HH];
__device__ __align__(256) __nv_bfloat16  d_emb_hi[VOCAB * EE], d_emb_lo[VOCAB * EE];

// ---------------- PTX helpers (baseline compute_103 PTX only) ------------
__device__ __forceinline__ uint32_t smem_u32(const void* p) {
    uint32_t a;
    asm("{ .reg .u64 t; cvta.to.shared.u64 t, %1; cvt.u32.u64 %0, t; }" : "=r"(a) : "l"(p));
    return a;
}
#define CP_ASYNC16(dst, src) \
    asm volatile("cp.async.cg.shared.global.L2::128B [%0], [%1], 16;" :: "r"(dst), "l"(src))
#define CP_COMMIT() asm volatile("cp.async.commit_group;" ::: "memory")
template<int n> __device__ __forceinline__ void cp_wait() {
    asm volatile("cp.async.wait_group %0;" :: "n"(n) : "memory");
}
#define LDMATRIX_X4(r0, r1, r2, r3, addr) \
    asm volatile("ldmatrix.sync.aligned.m8n8.x4.shared.b16 {%0,%1,%2,%3}, [%4];" \
        : "=r"(r0), "=r"(r1), "=r"(r2), "=r"(r3) : "r"(addr))
#define MMA_BF16(c, a, b) \
    asm volatile("mma.sync.aligned.m16n8k16.row.col.f32.bf16.bf16.f32 " \
        "{%0,%1,%2,%3}, {%4,%5,%6,%7}, {%8,%9}, {%0,%1,%2,%3};" \
        : "+f"((c)[0]), "+f"((c)[1]), "+f"((c)[2]), "+f"((c)[3]) \
        : "r"((a)[0]), "r"((a)[1]), "r"((a)[2]), "r"((a)[3]), "r"((b)[0]), "r"((b)[1]))

__device__ __forceinline__ float sigf(float x) { return 1.0f / (1.0f + __expf(-x)); }

// smem layout: [0,131072) operand double-buffer, [131072,196608) xg tile (MODE 1)
#define SMEM_OPS   131072
#define SMEM_XG    65536
#define SMEM_STEP  (SMEM_OPS + SMEM_XG)

// ---------------- bf16-split HMMA GEMM ----------------
// C[M,N] = (Ahi+Alo)[M,K] * (Bhi+Blo)[N,K]^T via hi*hi + hi*lo + lo*hi, fp32 accum.
// CTA 128x128, BK=64, 8 warps (2Mx4N), warp 64x32. Shared-fragment schedule.
// MODE 0: outp = C + bias (fp32), optional M guard (vocab GEMM).
// MODE 1: fused LSTM cell; xg row gathered by token, prefetched to smem.
template<int KDIM, int MODE, bool MGUARD>
__global__ __launch_bounds__(256, 1)
void hgemm(const __nv_bfloat16* __restrict__ Ahi, const __nv_bfloat16* __restrict__ Alo,
           const __nv_bfloat16* __restrict__ Bhi, const __nv_bfloat16* __restrict__ Blo,
           const float* __restrict__ bias,
           const float* __restrict__ xgv, const int* __restrict__ tokstep,
           float* __restrict__ outp,
           float* __restrict__ cst, __nv_bfloat16* __restrict__ hhi, __nv_bfloat16* __restrict__ hlo,
           int N, int Mlimit)
{
    extern __shared__ __align__(1024) char smem[];
    const uint32_t sb = smem_u32(smem);
    const int tid  = threadIdx.x;
    const int wid  = tid >> 5, lane = tid & 31;
    const int wm   = wid & 1,  wn   = wid >> 1;
    const int bm   = blockIdx.y * 128, bn = blockIdx.x * 128;
    constexpr int NC = KDIM / 64;

    // ---- loader mapping: 16 cp.async x 16B per thread per chunk ----
    const int lrow = tid >> 3;   // 0..31
    const int lj   = tid & 7;
    size_t arow[4];
#pragma unroll
    for (int q = 0; q < 4; ++q) {
        int r = bm + q * 32 + lrow;
        if (MGUARD && r >= Mlimit) r = Mlimit - 1;
        arow[q] = (size_t)r;
    }

    auto load_chunk = [&](int ch, int buf) {
        const int k0 = ch << 6;
#pragma unroll
        for (int i = 0; i < 16; ++i) {
            const int t = i >> 2, q = i & 3;
            const int row = q * 32 + lrow;
            const __nv_bfloat16* base;
            size_t grow;
            if      (t == 0) { base = Ahi; grow = arow[q]; }
            else if (t == 1) { base = Alo; grow = arow[q]; }
            else if (t == 2) { base = Bhi; grow = (size_t)(bn + row); }
            else             { base = Blo; grow = (size_t)(bn + row); }
            const char* src = (const char*)base + (grow * KDIM + k0) * 2 + lj * 16;
            uint32_t off = (uint32_t)(row * 128 + lj * 16);
            off ^= ((off >> 3) & 0x70);
            CP_ASYNC16(sb + (uint32_t)(buf * 65536 + t * 16384) + off, src);
        }
        CP_COMMIT();
    };

    // ---- MODE 1: prefetch the token-gathered xg tile into smem ----
    if (MODE == 1) {
#pragma unroll
        for (int i = 0; i < 16; ++i) {
            const int id  = i * 256 + tid;
            const int row = id >> 5, c16 = id & 31;
            const float* src = xgv + (size_t)tokstep[bm + row] * G4 + bn + c16 * 4;
            CP_ASYNC16(sb + SMEM_OPS + (uint32_t)id * 16, src);
        }
        CP_COMMIT();
    }

    float acc[4][4][4];
#pragma unroll
    for (int im = 0; im < 4; ++im)
#pragma unroll
        for (int in_ = 0; in_ < 4; ++in_)
#pragma unroll
            for (int r = 0; r < 4; ++r) acc[im][in_][r] = 0.0f;

    // ---- pipelined main loop ----
    load_chunk(0, 0);
    for (int ch = 0; ch < NC; ++ch) {
        if (ch + 1 < NC) { load_chunk(ch + 1, (ch + 1) & 1); cp_wait<1>(); }
        else             { cp_wait<0>(); }
        __syncthreads();

        const uint32_t base_buf = sb + (uint32_t)((ch & 1) * 65536);
#pragma unroll
        for (int ks = 0; ks < 4; ++ks) {
            uint32_t a_[4][4], b0_[4][2], b1_[4][2];
            // A-hi fragments
#pragma unroll
            for (int im = 0; im < 4; ++im) {
                const int r  = wm * 64 + im * 16 + ((lane >> 3) & 1) * 8 + (lane & 7);
                const int cb = ks * 32 + ((lane >> 4) & 1) * 16;
                uint32_t off = (uint32_t)(r * 128 + cb);
                off ^= ((off >> 3) & 0x70);
                LDMATRIX_X4(a_[im][0], a_[im][1], a_[im][2], a_[im][3], base_buf + off);
            }
            // B-hi and B-lo fragments
#pragma unroll
            for (int ib = 0; ib < 2; ++ib) {
                const int r  = wn * 32 + ib * 16 + ((lane >> 4) & 1) * 8 + (lane & 7);
                const int cb = ks * 32 + ((lane >> 3) & 1) * 16;
                uint32_t off = (uint32_t)(r * 128 + cb);
                off ^= ((off >> 3) & 0x70);
                uint32_t t0, t1, t2, t3;
                LDMATRIX_X4(t0, t1, t2, t3, base_buf + 32768u + off);
                b0_[2*ib][0] = t0; b0_[2*ib][1] = t1; b0_[2*ib+1][0] = t2; b0_[2*ib+1][1] = t3;
                LDMATRIX_X4(t0, t1, t2, t3, base_buf + 49152u + off);
                b1_[2*ib][0] = t0; b1_[2*ib][1] = t1; b1_[2*ib+1][0] = t2; b1_[2*ib+1][1] = t3;
            }
            // Ahi*Bhi and Ahi*Blo share A fragments
#pragma unroll
            for (int im = 0; im < 4; ++im)
#pragma unroll
                for (int in_ = 0; in_ < 4; ++in_) {
                    MMA_BF16(acc[im][in_], a_[im], b0_[in_]);
                    MMA_BF16(acc[im][in_], a_[im], b1_[in_]);
                }
            // A-lo fragments reuse registers; Alo*Bhi
#pragma unroll
            for (int im = 0; im < 4; ++im) {
                const int r  = wm * 64 + im * 16 + ((lane >> 3) & 1) * 8 + (lane & 7);
                const int cb = ks * 32 + ((lane >> 4) & 1) * 16;
                uint32_t off = (uint32_t)(r * 128 + cb);
                off ^= ((off >> 3) & 0x70);
                LDMATRIX_X4(a_[im][0], a_[im][1], a_[im][2], a_[im][3], base_buf + 16384u + off);
            }
#pragma unroll
            for (int im = 0; im < 4; ++im)
#pragma unroll
                for (int in_ = 0; in_ < 4; ++in_)
                    MMA_BF16(acc[im][in_], a_[im], b0_[in_]);
        }
        __syncthreads();
    }

    // ---- epilogue ----
    if (MODE == 0) {
#pragma unroll
        for (int im = 0; im < 4; ++im) {
#pragma unroll
            for (int in_ = 0; in_ < 4; ++in_) {
                const int row = bm + wm * 64 + im * 16 + (lane >> 2);
                const int col = bn + wn * 32 + in_ * 8 + 2 * (lane & 3);
                const float b0 = bias ? bias[col] : 0.0f;
                const float b1 = bias ? bias[col + 1] : 0.0f;
                if (!MGUARD || row < Mlimit) {
                    float* p0 = outp + (size_t)row * N + col;
                    *(float2*)p0 = make_float2(acc[im][in_][0] + b0, acc[im][in_][1] + b1);
                }
                if (!MGUARD || row + 8 < Mlimit) {
                    float* p1 = outp + (size_t)(row + 8) * N + col;
                    *(float2*)p1 = make_float2(acc[im][in_][2] + b0, acc[im][in_][3] + b1);
                }
            }
        }
    } else {
        // stage gates [128][132] fp32 in operand smem (now free)
        float* gs = (float*)smem;
        const float* xs = (const float*)(smem + SMEM_OPS);
#pragma unroll
        for (int im = 0; im < 4; ++im) {
#pragma unroll
            for (int in_ = 0; in_ < 4; ++in_) {
                const int row = wm * 64 + im * 16 + (lane >> 2);
                const int col = wn * 32 + in_ * 8 + 2 * (lane & 3);
                gs[row * 132 + col]           = acc[im][in_][0];
                gs[row * 132 + col + 1]       = acc[im][in_][1];
                gs[(row + 8) * 132 + col]     = acc[im][in_][2];
                gs[(row + 8) * 132 + col + 1] = acc[im][in_][3];
            }
        }
        __syncthreads();
#pragma unroll
        for (int it = 0; it < 16; ++it) {
            const int idx = tid + it * 256;
            const int row = idx >> 5;
            const int u   = idx & 31;
            const float g0 = gs[row * 132 + 4 * u];
            const float g1 = gs[row * 132 + 4 * u + 1];
            const float g2 = gs[row * 132 + 4 * u + 2];
            const float g3 = gs[row * 132 + 4 * u + 3];
            const float4 x = *(const float4*)(xs + row * 128 + 4 * u);
            const float ig = sigf(g0 + x.x);
            const float fg = sigf(g1 + x.y);
            const float gg = tanhf(g2 + x.z);
            const float og = sigf(g3 + x.w);
            const size_t cidx = (size_t)(bm + row) * HH + (bn >> 2) + u;
            const float cn = fg * cst[cidx] + ig * gg;
            cst[cidx] = cn;
            const float h = og * tanhf(cn);
            const __nv_bfloat16 hi = __float2bfloat16_rn(h);
            hhi[cidx] = hi;
            hlo[cidx] = __float2bfloat16_rn(h - __bfloat162float(hi));
        }
    }
}

// ---------------- packing (vectorized, one kernel) ----------------
__device__ __forceinline__ unsigned short bfbits(__nv_bfloat16 h) {
    unsigned short s; memcpy(&s, &h, 2); return s;
}
__device__ __forceinline__ void split_store4(float4 v, __nv_bfloat16* hip, __nv_bfloat16* lop, size_t i4) {
    float f[4] = {v.x, v.y, v.z, v.w};
    unsigned short hb[4], lb[4];
#pragma unroll
    for (int i = 0; i < 4; ++i) {
        const __nv_bfloat16 h = __float2bfloat16_rn(f[i]);
        hb[i] = bfbits(h);
        lb[i] = bfbits(__float2bfloat16_rn(f[i] - __bfloat162float(h)));
    }
    uint2 hv, lv;
    hv.x = (uint32_t)hb[0] | ((uint32_t)hb[1] << 16);
    hv.y = (uint32_t)hb[2] | ((uint32_t)hb[3] << 16);
    lv.x = (uint32_t)lb[0] | ((uint32_t)lb[1] << 16);
    lv.y = (uint32_t)lb[2] | ((uint32_t)lb[3] << 16);
    *(uint2*)(hip + i4 * 4) = hv;
    *(uint2*)(lop + i4 * 4) = lv;
}

__global__ void pack_all(const int* __restrict__ m,
                         const float* __restrict__ emb,
                         const float* __restrict__ W_ih, const float* __restrict__ W_hh,
                         const float* __restrict__ W_out,
                         const float* __restrict__ b_ih, const float* __restrict__ b_hh)
{
    const size_t idx = (size_t)blockIdx.x * blockDim.x + threadIdx.x;
    // emb: 10000*512/4 = 1,280,000 float4s
    if (idx < (size_t)VOCAB * EE / 4)
        split_store4(((const float4*)emb)[idx], d_emb_hi, d_emb_lo, idx);
    // W_hh permuted rows: 4096*1024/4 = 1,048,576
    if (idx < (size_t)G4 * HH / 4) {
        const int n = (int)(idx >> 8), kk = ((int)idx & 255) * 4;
        const int srcrow = (n & 3) * HH + (n >> 2);
        const float4 v = *(const float4*)(W_hh + (size_t)srcrow * HH + kk);
        split_store4(v, d_whh_hi, d_whh_lo, idx);
    }
    // W_ih permuted rows: 4096*512/4 = 524,288
    if (idx < (size_t)G4 * EE / 4) {
        const int n = (int)(idx >> 7), kk = ((int)idx & 127) * 4;
        const int srcrow = (n & 3) * HH + (n >> 2);
        const float4 v = *(const float4*)(W_ih + (size_t)srcrow * EE + kk);
        split_store4(v, d_wih_hi, d_wih_lo, idx);
    }
    // W_out direct: 2048*1024/4 = 524,288
    if (idx < (size_t)NIMG * HH / 4)
        split_store4(((const float4*)W_out)[idx], d_wout_hi, d_wout_lo, idx);
    // bias (permuted)
    if (idx < G4) {
        const int gt = (int)idx & 3, u = (int)idx >> 2;
        d_bsum[idx] = b_ih[gt * HH + u] + b_hh[gt * HH + u];
    }
    // h/c init: c 524288 floats = 131072 float4; h bufs 524288 bf16 = 131072 uint2... (1MB/8B)
    if (idx < (size_t)BB * HH / 4) {
        ((float4*)d_c)[idx] = make_float4(0.f, 0.f, 0.f, 0.f);
        const uint2 z = make_uint2(0u, 0u);
        ((uint2*)&d_hhi[0][0])[idx] = z;
        ((uint2*)&d_hlo[0][0])[idx] = z;
    }
    // token transpose: [T][B] <- m[B][T]
    if (idx < (size_t)TT * BB) {
        const int t = (int)idx >> 9, b = (int)idx & 511;
        d_tok[idx] = m[b * TT + t];
    }
}

// ---------------- launch ----------------
extern "C" void kernel_launch(void* const* d_in, const int* in_sizes, int n_in,
                              void* d_out, int out_size)
{
    const int*   m     = (const int*)  d_in[0];
    const float* emb   = (const float*)d_in[1];
    const float* W_ih  = (const float*)d_in[2];
    const float* W_hh  = (const float*)d_in[3];
    const float* b_ih  = (const float*)d_in[4];
    const float* b_hh  = (const float*)d_in[5];
    const float* W_out = (const float*)d_in[6];
    const float* b_out = (const float*)d_in[7];
    float* out = (float*)d_out;

    float *Xg, *cst, *bsum; int* tok;
    __nv_bfloat16 *hhi0, *hlo0, *hhi1, *hlo1;
    __nv_bfloat16 *wih_hi, *wih_lo, *whh_hi, *whh_lo, *wout_hi, *wout_lo, *emb_hi, *emb_lo;
    cudaGetSymbolAddress((void**)&Xg,   d_Xg);
    cudaGetSymbolAddress((void**)&cst,  d_c);
    cudaGetSymbolAddress((void**)&bsum, d_bsum);
    cudaGetSymbolAddress((void**)&tok,  d_tok);
    {
        __nv_bfloat16* p;
        cudaGetSymbolAddress((void**)&p, d_hhi); hhi0 = p; hhi1 = p + BB * HH;
        cudaGetSymbolAddress((void**)&p, d_hlo); hlo0 = p; hlo1 = p + BB * HH;
        cudaGetSymbolAddress((void**)&p, d_wih_hi);  wih_hi = p;
        cudaGetSymbolAddress((void**)&p, d_wih_lo);  wih_lo = p;
        cudaGetSymbolAddress((void**)&p, d_whh_hi);  whh_hi = p;
        cudaGetSymbolAddress((void**)&p, d_whh_lo);  whh_lo = p;
        cudaGetSymbolAddress((void**)&p, d_wout_hi); wout_hi = p;
        cudaGetSymbolAddress((void**)&p, d_wout_lo); wout_lo = p;
        cudaGetSymbolAddress((void**)&p, d_emb_hi);  emb_hi = p;
        cudaGetSymbolAddress((void**)&p, d_emb_lo);  emb_lo = p;
    }

    cudaFuncSetAttribute(hgemm<EE, 0, true>,  cudaFuncAttributeMaxDynamicSharedMemorySize, SMEM_OPS);
    cudaFuncSetAttribute(hgemm<HH, 1, false>, cudaFuncAttributeMaxDynamicSharedMemorySize, SMEM_STEP);
    cudaFuncSetAttribute(hgemm<HH, 0, false>, cudaFuncAttributeMaxDynamicSharedMemorySize, SMEM_OPS);

    // 1) pack everything (weights, emb, bias, state init, token transpose)
    pack_all<<<(VOCAB * EE / 4 + 255) / 256, 256>>>(m, emb, W_ih, W_hh, W_out, b_ih, b_hh);

    // 2) per-VOCAB gate table: Xg_v[v] = emb[v] @ W_ih^T + (b_ih+b_hh)  (permuted cols)
    {
        dim3 grid(G4 / 128, MVPAD / 128);   // 32 x 79
        hgemm<EE, 0, true><<<grid, 256, SMEM_OPS>>>(
            emb_hi, emb_lo, wih_hi, wih_lo, bsum, nullptr, nullptr, Xg,
            nullptr, nullptr, nullptr, G4, VOCAB);
    }

    // 3) recurrent loop: fused GEMM+LSTM per step; xg gathered by token in-kernel
    {
        dim3 grid(G4 / 128, BB / 128);      // 32 x 4
        for (int t = 0; t < TT; ++t) {
            const int in  = t & 1;
            __nv_bfloat16* ahi = in ? hhi1 : hhi0;
            __nv_bfloat16* alo = in ? hlo1 : hlo0;
            __nv_bfloat16* ohi = in ? hhi0 : hhi1;
            __nv_bfloat16* olo = in ? hlo0 : hlo1;
            hgemm<HH, 1, false><<<grid, 256, SMEM_STEP>>>(
                ahi, alo, whh_hi, whh_lo, nullptr, Xg, tok + t * BB, nullptr,
                cst, ohi, olo, G4, 0);
        }
    }

    // 4) out = h @ W_out^T + b_out   (after 64 steps final h is in buffer 0)
    {
        dim3 grid(NIMG / 128, BB / 128);    // 16 x 4
        hgemm<HH, 0, false><<<grid, 256, SMEM_OPS>>>(
            hhi0, hlo0, wout_hi, wout_lo, b_out, nullptr, nullptr, out,
            nullptr, nullptr, nullptr, NIMG, 0);
    }
}